// round 3
// baseline (speedup 1.0000x reference)
#include <cuda_runtime.h>

// ---------------- problem constants ----------------
#define BATCH 32
#define HIN   256
#define WIN   256
#define H1    128
#define W1P   128
#define C1    32
#define H2    64
#define W2P   64
#define C2    64
#define FLAT  262144            // 64*64*64
#define NJ    128
#define NCHUNK 512              // split-K chunks for FC1
#define KC     512              // K per chunk (512*512 = 262144)

// ---------------- scratch (static device globals; no runtime alloc) ----------------
__device__ float g_conv1[(size_t)BATCH * H1 * W1P * C1];     // 67 MB
__device__ float g_conv2[(size_t)BATCH * FLAT];              // 33.5 MB
__device__ float g_part[(size_t)NCHUNK * BATCH * NJ];        // 8 MB
__device__ float g_part2[16 * BATCH * NJ];                   // 256 KB
__device__ float g_xfc[BATCH * NJ];
__device__ float g_theta[BATCH * 6];

// ---------------- packed fp32x2 helpers (bit-exact 2x fp32 FMA) ----------------
__device__ __forceinline__ unsigned long long pack2(float lo, float hi) {
    unsigned long long r;
    asm("mov.b64 %0, {%1,%2};" : "=l"(r) : "f"(lo), "f"(hi));
    return r;
}
__device__ __forceinline__ void unpack2(unsigned long long v, float& lo, float& hi) {
    asm("mov.b64 {%0,%1}, %2;" : "=f"(lo), "=f"(hi) : "l"(v));
}
__device__ __forceinline__ unsigned long long ffma2(unsigned long long a,
                                                    unsigned long long b,
                                                    unsigned long long c) {
    unsigned long long d;
    asm("fma.rn.f32x2 %0, %1, %2, %3;" : "=l"(d) : "l"(a), "l"(b), "l"(c));
    return d;
}

// =====================================================================
// conv1: [32,256,256,3] -> [32,128,128,32], 3x3 stride2 SAME (pad lo=0, hi=1), relu
// One thread per output pixel, all 32 output channels (16 f32x2 accumulators).
// =====================================================================
__global__ __launch_bounds__(256) void conv1_kernel(const float* __restrict__ in,
                                                    const float* __restrict__ k1,
                                                    const float* __restrict__ b1) {
    __shared__ __align__(16) float wS[864];          // 3*3*3*32
    int tid = threadIdx.x;
    for (int i = tid; i < 864; i += 256) wS[i] = k1[i];
    __syncthreads();

    int pid = blockIdx.x * 256 + tid;                 // < 32*128*128
    int b   = pid >> 14;
    int rem = pid & 16383;
    int oh  = rem >> 7;
    int ow  = rem & 127;

    unsigned long long acc[16];
#pragma unroll
    for (int i = 0; i < 16; i++) acc[i] = 0ULL;

#pragma unroll
    for (int r = 0; r < 3; r++) {
        int ih = 2 * oh + r;
        bool okh = (ih < HIN);
#pragma unroll
        for (int s = 0; s < 3; s++) {
            int iw = 2 * ow + s;
            bool ok = okh && (iw < WIN);
            const float* ip = in + ((size_t)(b * HIN + ih) * WIN + iw) * 3;
            float v[3];
            v[0] = ok ? ip[0] : 0.f;
            v[1] = ok ? ip[1] : 0.f;
            v[2] = ok ? ip[2] : 0.f;
#pragma unroll
            for (int ci = 0; ci < 3; ci++) {
                unsigned long long vv = pack2(v[ci], v[ci]);
                const ulonglong2* wp =
                    (const ulonglong2*)&wS[((r * 3 + s) * 3 + ci) * 32];
#pragma unroll
                for (int p = 0; p < 8; p++) {
                    ulonglong2 wq = wp[p];
                    acc[p * 2 + 0] = ffma2(vv, wq.x, acc[p * 2 + 0]);
                    acc[p * 2 + 1] = ffma2(vv, wq.y, acc[p * 2 + 1]);
                }
            }
        }
    }

    float* op = g_conv1 + ((size_t)(b * H1 + oh) * W1P + ow) * C1;
#pragma unroll
    for (int i = 0; i < 16; i++) {
        float a0, a1;
        unpack2(acc[i], a0, a1);
        float2 st;
        st.x = fmaxf(a0 + b1[2 * i + 0], 0.f);
        st.y = fmaxf(a1 + b1[2 * i + 1], 0.f);
        *(float2*)(op + 2 * i) = st;
    }
}

// =====================================================================
// conv2: [32,128,128,32] -> [32,64,64,64], 3x3 stride2 SAME, relu
// Block: 512 threads, tile 16x16 output pixels, all 64 channels.
// smem: weights 72KB + input tile 33x33x32 (136KB) = 208KB (opt-in).
// Thread: 4 pixels x 8 channels = 16 f32x2 accumulators. 16 warps/SM.
// =====================================================================
#define SM2_W  18432              /* 3*3*32*64 weight floats */
#define SM2_I  (33 * 33 * 32)     /* 34848 input floats */
#define SM2_BYTES ((SM2_W + SM2_I) * 4)

__global__ __launch_bounds__(512, 1) void conv2_kernel(const float* __restrict__ k2,
                                                       const float* __restrict__ b2) {
    extern __shared__ __align__(16) float sm[];
    float* wS  = sm;
    float* inS = sm + SM2_W;

    int tid = threadIdx.x;
    int b   = blockIdx.z;
    int oh0 = blockIdx.y * 16;
    int ow0 = blockIdx.x * 16;
    int ih0 = oh0 * 2, iw0 = ow0 * 2;

    // weights: 18432 floats = 4608 float4
    {
        const float4* src = (const float4*)k2;
        float4* dst = (float4*)wS;
        for (int i = tid; i < SM2_W / 4; i += 512) dst[i] = src[i];
    }
    // input tile: 33x33 pixels x 8 float4
    for (int i = tid; i < 33 * 33 * 8; i += 512) {
        int rr   = i / 264;           // 33*8
        int rest = i - rr * 264;
        int cc   = rest >> 3;
        int v4   = rest & 7;
        int ih = ih0 + rr, iw = iw0 + cc;
        float4 v = {0.f, 0.f, 0.f, 0.f};
        if (ih < H1 && iw < W1P)
            v = *(const float4*)&g_conv1[(((size_t)(b * H1 + ih) * W1P + iw) * C1) + v4 * 4];
        *(float4*)&inS[(rr * 33 + cc) * 32 + v4 * 4] = v;
    }
    __syncthreads();

    int ps = tid >> 3;          // 0..63 pixel set (4 pixels each)
    int cg = tid & 7;           // channel group: channels cg*8 .. cg*8+7

    int base[4];
#pragma unroll
    for (int q = 0; q < 4; q++) {
        int lp = ps * 4 + q;
        int ly = lp >> 4, lx = lp & 15;
        base[q] = (ly * 2 * 33 + lx * 2) * 32;
    }

    unsigned long long acc[16];
#pragma unroll
    for (int i = 0; i < 16; i++) acc[i] = 0ULL;

    for (int rs = 0; rs < 9; rs++) {
        int r = rs / 3, s = rs - r * 3;
        const float* wrow = wS + rs * 2048 + cg * 8;   // [rs][ci][64] layout
        int ioff = (r * 33 + s) * 32;
#pragma unroll 8
        for (int ci = 0; ci < 32; ci++) {
            ulonglong2 wA = *(const ulonglong2*)(wrow + ci * 64);
            ulonglong2 wB = *(const ulonglong2*)(wrow + ci * 64 + 4);
#pragma unroll
            for (int q = 0; q < 4; q++) {
                float v = inS[base[q] + ioff + ci];
                unsigned long long vv = pack2(v, v);
                acc[q * 4 + 0] = ffma2(vv, wA.x, acc[q * 4 + 0]);
                acc[q * 4 + 1] = ffma2(vv, wA.y, acc[q * 4 + 1]);
                acc[q * 4 + 2] = ffma2(vv, wB.x, acc[q * 4 + 2]);
                acc[q * 4 + 3] = ffma2(vv, wB.y, acc[q * 4 + 3]);
            }
        }
    }

#pragma unroll
    for (int q = 0; q < 4; q++) {
        int lp = ps * 4 + q;
        int ly = lp >> 4, lx = lp & 15;
        float* op = g_conv2 +
                    ((size_t)(b * H2 + oh0 + ly) * W2P + (ow0 + lx)) * C2 + cg * 8;
#pragma unroll
        for (int p = 0; p < 4; p++) {
            float a0, a1;
            unpack2(acc[q * 4 + p], a0, a1);
            float2 st;
            st.x = fmaxf(a0 + b2[cg * 8 + 2 * p + 0], 0.f);
            st.y = fmaxf(a1 + b2[cg * 8 + 2 * p + 1], 0.f);
            *(float2*)(op + 2 * p) = st;
        }
    }
}

// =====================================================================
// FC1 split-K: partial[chunk][b][j] = sum_{k in chunk} x[b,k] * w1[k,j]
// 512 chunks of K=512. 256 threads: each owns 2 batches x 8 j.
// x prepacked as duplicated f32x2 in smem -> 12-instr inner body per 8 ffma2.
// =====================================================================
__global__ __launch_bounds__(256) void fc1_kernel(const float* __restrict__ w1) {
    __shared__ __align__(16) float wS[32 * NJ];                 // 16 KB
    __shared__ __align__(16) unsigned long long xU[32 * 33];    // [b][k], padded

    int tid   = threadIdx.x;
    int chunk = blockIdx.x;
    int kbase = chunk * KC;

    int jg = tid & 15;   // j = jg*8 .. +7
    int bg = tid >> 4;   // batches bg*2, bg*2+1

    unsigned long long acc[8];
#pragma unroll
    for (int i = 0; i < 8; i++) acc[i] = 0ULL;

    for (int kt = 0; kt < KC / 32; kt++) {
        int k0 = kbase + kt * 32;
        {
            const float4* w1v = (const float4*)(w1 + (size_t)k0 * NJ);
            float4* wSv = (float4*)wS;
            for (int i = tid; i < 1024; i += 256) wSv[i] = w1v[i];
        }
        for (int i = tid; i < 1024; i += 256) {
            int bb = i >> 5, kk = i & 31;
            float x = g_conv2[(size_t)bb * FLAT + k0 + kk];
            xU[bb * 33 + kk] = pack2(x, x);
        }
        __syncthreads();
#pragma unroll
        for (int kk = 0; kk < 32; kk++) {
            ulonglong2 w0 = *(const ulonglong2*)&wS[kk * NJ + jg * 8];
            ulonglong2 w1q = *(const ulonglong2*)&wS[kk * NJ + jg * 8 + 4];
            unsigned long long xa = xU[(bg * 2 + 0) * 33 + kk];
            unsigned long long xb = xU[(bg * 2 + 1) * 33 + kk];
            acc[0] = ffma2(xa, w0.x, acc[0]);
            acc[1] = ffma2(xa, w0.y, acc[1]);
            acc[2] = ffma2(xa, w1q.x, acc[2]);
            acc[3] = ffma2(xa, w1q.y, acc[3]);
            acc[4] = ffma2(xb, w0.x, acc[4]);
            acc[5] = ffma2(xb, w0.y, acc[5]);
            acc[6] = ffma2(xb, w1q.x, acc[6]);
            acc[7] = ffma2(xb, w1q.y, acc[7]);
        }
        __syncthreads();
    }

    float* pp = g_part + (size_t)chunk * BATCH * NJ;
#pragma unroll
    for (int bl = 0; bl < 2; bl++) {
        float a0, a1, a2, a3, a4, a5, a6, a7;
        unpack2(acc[bl * 4 + 0], a0, a1);
        unpack2(acc[bl * 4 + 1], a2, a3);
        unpack2(acc[bl * 4 + 2], a4, a5);
        unpack2(acc[bl * 4 + 3], a6, a7);
        float4 s0 = {a0, a1, a2, a3};
        float4 s1 = {a4, a5, a6, a7};
        float* row = pp + (bg * 2 + bl) * NJ + jg * 8;
        *(float4*)(row + 0) = s0;
        *(float4*)(row + 4) = s1;
    }
}

// reduce stage A: sum 32 chunks per group -> g_part2[16][4096]
__global__ __launch_bounds__(256) void fc1_reduceA_kernel() {
    int idx = blockIdx.x * 256 + threadIdx.x;   // 0..4095
    int g   = blockIdx.y;                       // 0..15
    float s = 0.f;
#pragma unroll
    for (int c = 0; c < 32; c++)
        s += g_part[(size_t)(g * 32 + c) * (BATCH * NJ) + idx];
    g_part2[g * (BATCH * NJ) + idx] = s;
}

// reduce stage B: sum 16 groups + bias + relu -> g_xfc
__global__ __launch_bounds__(256) void fc1_reduceB_kernel(const float* __restrict__ d1) {
    int idx = blockIdx.x * 256 + threadIdx.x;   // 0..4095
    float s = 0.f;
#pragma unroll
    for (int g = 0; g < 16; g++)
        s += g_part2[g * (BATCH * NJ) + idx];
    int j = idx & 127;
    g_xfc[idx] = fmaxf(s + d1[j], 0.f);
}

// theta = x @ w2 + d2   (tiny)
__global__ void fc2_kernel(const float* __restrict__ w2, const float* __restrict__ d2) {
    int tid = threadIdx.x;
    if (tid >= BATCH * 6) return;
    int b = tid / 6, i = tid % 6;
    float s = d2[i];
    const float* x = g_xfc + b * NJ;
#pragma unroll 8
    for (int j = 0; j < NJ; j++) s += x[j] * w2[j * 6 + i];
    g_theta[tid] = s;
}

// =====================================================================
// grid_sample: bilinear, zero padding OOB. One thread per output pixel (3 ch).
// =====================================================================
__global__ __launch_bounds__(256) void sample_kernel(const float* __restrict__ in,
                                                     float* __restrict__ out) {
    int pid = blockIdx.x * 256 + threadIdx.x;   // < 32*256*256
    int b   = pid >> 16;
    int rem = pid & 65535;
    int y   = rem >> 8;
    int x   = rem & 255;

    const float* th = g_theta + b * 6;
    float t0 = th[0], t1 = th[1], t2 = th[2];
    float t3 = th[3], t4 = th[4], t5 = th[5];

    float X = (2.f * (float)x + 1.f) * (1.f / 256.f) - 1.f;
    float Y = (2.f * (float)y + 1.f) * (1.f / 256.f) - 1.f;
    float gx = t0 * X + t1 * Y + t2;
    float gy = t3 * X + t4 * Y + t5;
    float px = (gx + 1.f) * 128.f - 0.5f;
    float py = (gy + 1.f) * 128.f - 0.5f;

    float x0f = floorf(px), y0f = floorf(py);
    float wx1 = px - x0f, wx0 = 1.f - wx1;
    float wy1 = py - y0f, wy0 = 1.f - wy1;
    int ix0 = (int)x0f, iy0 = (int)y0f;
    int ix1 = ix0 + 1,  iy1 = iy0 + 1;

    float o0 = 0.f, o1 = 0.f, o2 = 0.f;
    const float* base = in + (size_t)b * HIN * WIN * 3;

    {
        int yi = iy0, xi = ix0; float w = wy0 * wx0;
        if (xi >= 0 && xi < WIN && yi >= 0 && yi < HIN) {
            const float* p = base + ((size_t)yi * WIN + xi) * 3;
            o0 += w * p[0]; o1 += w * p[1]; o2 += w * p[2];
        }
    }
    {
        int yi = iy0, xi = ix1; float w = wy0 * wx1;
        if (xi >= 0 && xi < WIN && yi >= 0 && yi < HIN) {
            const float* p = base + ((size_t)yi * WIN + xi) * 3;
            o0 += w * p[0]; o1 += w * p[1]; o2 += w * p[2];
        }
    }
    {
        int yi = iy1, xi = ix0; float w = wy1 * wx0;
        if (xi >= 0 && xi < WIN && yi >= 0 && yi < HIN) {
            const float* p = base + ((size_t)yi * WIN + xi) * 3;
            o0 += w * p[0]; o1 += w * p[1]; o2 += w * p[2];
        }
    }
    {
        int yi = iy1, xi = ix1; float w = wy1 * wx1;
        if (xi >= 0 && xi < WIN && yi >= 0 && yi < HIN) {
            const float* p = base + ((size_t)yi * WIN + xi) * 3;
            o0 += w * p[0]; o1 += w * p[1]; o2 += w * p[2];
        }
    }

    float* op = out + (size_t)pid * 3;
    op[0] = o0; op[1] = o1; op[2] = o2;
}

// =====================================================================
// launch
// =====================================================================
extern "C" void kernel_launch(void* const* d_in, const int* in_sizes, int n_in,
                              void* d_out, int out_size) {
    const float* inputs = (const float*)d_in[0];
    const float* k1     = (const float*)d_in[1];
    const float* b1     = (const float*)d_in[2];
    const float* k2     = (const float*)d_in[3];
    const float* b2     = (const float*)d_in[4];
    const float* w1     = (const float*)d_in[5];
    const float* d1     = (const float*)d_in[6];
    const float* w2     = (const float*)d_in[7];
    const float* d2     = (const float*)d_in[8];
    float* out = (float*)d_out;

    static int smem_set = 0;
    if (!smem_set) {
        cudaFuncSetAttribute(conv2_kernel, cudaFuncAttributeMaxDynamicSharedMemorySize,
                             SM2_BYTES);
        smem_set = 1;
    }

    conv1_kernel<<<(BATCH * H1 * W1P) / 256, 256>>>(inputs, k1, b1);

    dim3 g2(W2P / 16, H2 / 16, BATCH);   // (4, 4, 32)
    conv2_kernel<<<g2, 512, SM2_BYTES>>>(k2, b2);

    fc1_kernel<<<NCHUNK, 256>>>(w1);
    dim3 gra(16, 16);
    fc1_reduceA_kernel<<<gra, 256>>>();
    fc1_reduceB_kernel<<<16, 256>>>(d1);
    fc2_kernel<<<1, 192>>>(w2, d2);

    sample_kernel<<<(BATCH * HIN * WIN) / 256, 256>>>(inputs, out);
}

// round 7
// speedup vs baseline: 1.5521x; 1.5521x over previous
#include <cuda_runtime.h>

// ---------------- problem constants ----------------
#define BATCH 32
#define HIN   256
#define WIN   256
#define H1    128
#define W1P   128
#define C1    32
#define H2    64
#define W2P   64
#define C2    64
#define FLAT  262144            // 64*64*64
#define NJ    128
#define NCH2  256               // fc1 CTA count (each covers K=1024, 4 groups of 256)

// ---------------- scratch (static device globals; no runtime alloc) ----------------
__device__ float g_conv1[(size_t)BATCH * H1 * W1P * C1];     // 67 MB
__device__ float g_conv2[(size_t)BATCH * FLAT];              // 33.5 MB
__device__ float g_part[(size_t)1024 * BATCH * NJ];          // 16 MB (1024 partials)
__device__ float g_part2[16 * BATCH * NJ];                   // 256 KB
__device__ float g_xfc[BATCH * NJ];
__device__ float g_theta[BATCH * 6];

// ---------------- packed fp32x2 helpers (bit-exact 2x fp32 FMA) ----------------
__device__ __forceinline__ unsigned long long pack2(float lo, float hi) {
    unsigned long long r;
    asm("mov.b64 %0, {%1,%2};" : "=l"(r) : "f"(lo), "f"(hi));
    return r;
}
__device__ __forceinline__ void unpack2(unsigned long long v, float& lo, float& hi) {
    asm("mov.b64 {%0,%1}, %2;" : "=f"(lo), "=f"(hi) : "l"(v));
}
__device__ __forceinline__ unsigned long long ffma2(unsigned long long a,
                                                    unsigned long long b,
                                                    unsigned long long c) {
    unsigned long long d;
    asm("fma.rn.f32x2 %0, %1, %2, %3;" : "=l"(d) : "l"(a), "l"(b), "l"(c));
    return d;
}

// =====================================================================
// conv1: [32,256,256,3] -> [32,128,128,32], 3x3 s2 SAME (pad hi only), relu
// =====================================================================
__global__ __launch_bounds__(256) void conv1_kernel(const float* __restrict__ in,
                                                    const float* __restrict__ k1,
                                                    const float* __restrict__ b1) {
    __shared__ __align__(16) float wS[864];          // 3*3*3*32
    int tid = threadIdx.x;
    for (int i = tid; i < 864; i += 256) wS[i] = k1[i];
    __syncthreads();

    int pid = blockIdx.x * 256 + tid;                 // < 32*128*128
    int b   = pid >> 14;
    int rem = pid & 16383;
    int oh  = rem >> 7;
    int ow  = rem & 127;

    unsigned long long acc[16];
#pragma unroll
    for (int i = 0; i < 16; i++) acc[i] = 0ULL;

#pragma unroll
    for (int r = 0; r < 3; r++) {
        int ih = 2 * oh + r;
        bool okh = (ih < HIN);
#pragma unroll
        for (int s = 0; s < 3; s++) {
            int iw = 2 * ow + s;
            bool ok = okh && (iw < WIN);
            const float* ip = in + ((size_t)(b * HIN + ih) * WIN + iw) * 3;
            float v[3];
            v[0] = ok ? ip[0] : 0.f;
            v[1] = ok ? ip[1] : 0.f;
            v[2] = ok ? ip[2] : 0.f;
#pragma unroll
            for (int ci = 0; ci < 3; ci++) {
                unsigned long long vv = pack2(v[ci], v[ci]);
                const ulonglong2* wp =
                    (const ulonglong2*)&wS[((r * 3 + s) * 3 + ci) * 32];
#pragma unroll
                for (int p = 0; p < 8; p++) {
                    ulonglong2 wq = wp[p];
                    acc[p * 2 + 0] = ffma2(vv, wq.x, acc[p * 2 + 0]);
                    acc[p * 2 + 1] = ffma2(vv, wq.y, acc[p * 2 + 1]);
                }
            }
        }
    }

    float* op = g_conv1 + ((size_t)(b * H1 + oh) * W1P + ow) * C1;
#pragma unroll
    for (int i = 0; i < 16; i++) {
        float a0, a1;
        unpack2(acc[i], a0, a1);
        float2 st;
        st.x = fmaxf(a0 + b1[2 * i + 0], 0.f);
        st.y = fmaxf(a1 + b1[2 * i + 1], 0.f);
        *(float2*)(op + 2 * i) = st;
    }
}

// =====================================================================
// conv2 v3: [32,128,128,32] -> [32,64,64,64], 3x3 s2 SAME, relu.
// 256 threads, tile 16x16 px x 64 ch. Thread: 8 px (column) x 8 ch.
// Input smem: 8 planes (ci4) of 33x33 float4 -> aligned conflict-free LDS.128.
// Weights relaid out to 16B-per-cg stride -> conflict-free LDS.128.
// =====================================================================
#define SM2_W  18432                      /* weight floats */
#define SM2_I4 (8 * 33 * 33)              /* input float4 count = 8712 */
#define SM2_BYTES ((SM2_W + SM2_I4 * 4) * 4)   /* 213120 B */

__global__ __launch_bounds__(256, 1) void conv2_kernel(const float* __restrict__ k2,
                                                       const float* __restrict__ b2) {
    extern __shared__ __align__(16) float sm[];
    float*  wS  = sm;                         // relaid weights
    float4* inS = (float4*)(sm + SM2_W);      // 8 planes of 33*33

    int tid = threadIdx.x;
    int b   = blockIdx.z;
    int oh0 = blockIdx.y * 16;
    int ow0 = blockIdx.x * 16;
    int ih0 = oh0 * 2, iw0 = ow0 * 2;

    // weights: relayout k2[rs][ci][oc] -> wS[((rs*32+ci)*2+half)*8+cg][4]
    for (int i = tid; i < SM2_W; i += 256) {
        int rs  = i >> 11;
        int rem = i & 2047;
        int ci  = rem >> 6;
        int oc  = rem & 63;
        int cg = oc >> 3, half = (oc >> 2) & 1, f = oc & 3;
        wS[((((rs * 32 + ci) * 2 + half) * 8 + cg) << 2) + f] = k2[i];
    }
    // input planes: inS[ci4*1089 + iy*33 + ix]
    for (int i = tid; i < SM2_I4; i += 256) {
        int ci4 = i & 7;
        int p   = i >> 3;                 // 0..1088
        int iy  = p / 33, ix = p - iy * 33;
        int ih = ih0 + iy, iw = iw0 + ix;
        float4 v = {0.f, 0.f, 0.f, 0.f};
        if (ih < H1 && iw < W1P)
            v = *(const float4*)&g_conv1[(((size_t)(b * H1 + ih) * W1P + iw)) * C1 + ci4 * 4];
        inS[ci4 * 1089 + p] = v;
    }
    __syncthreads();

    int cg   = tid & 7;
    int pset = tid >> 3;          // 0..31
    int lx   = pset & 15;
    int hi   = pset >> 4;         // 0..1; thread pixel q: (ly, lx), ly = 2q + hi

    unsigned long long acc[8][4];
#pragma unroll
    for (int q = 0; q < 8; q++)
#pragma unroll
        for (int p = 0; p < 4; p++) acc[q][p] = 0ULL;

    const float4* wf4 = (const float4*)wS;

    for (int rs = 0; rs < 9; rs++) {
        int r = rs / 3, s = rs - r * 3;
        int rsoff = r * 33 + s;
        int pbase = rsoff + 2 * hi * 33 + 2 * lx;     // + 4q*33 per q
#pragma unroll 2
        for (int ci4 = 0; ci4 < 8; ci4++) {
            float4 v[8];
#pragma unroll
            for (int q = 0; q < 8; q++)
                v[q] = inS[ci4 * 1089 + pbase + q * 132];
#pragma unroll
            for (int cs = 0; cs < 4; cs++) {
                int ci = ci4 * 4 + cs;
                int wbase = ((rs * 32 + ci) * 2) * 8 + cg;
                ulonglong2 wA = *(const ulonglong2*)&wf4[wbase];
                ulonglong2 wB = *(const ulonglong2*)&wf4[wbase + 8];
#pragma unroll
                for (int q = 0; q < 8; q++) {
                    float x = cs == 0 ? v[q].x : cs == 1 ? v[q].y : cs == 2 ? v[q].z : v[q].w;
                    unsigned long long xx = pack2(x, x);
                    acc[q][0] = ffma2(xx, wA.x, acc[q][0]);
                    acc[q][1] = ffma2(xx, wA.y, acc[q][1]);
                    acc[q][2] = ffma2(xx, wB.x, acc[q][2]);
                    acc[q][3] = ffma2(xx, wB.y, acc[q][3]);
                }
            }
        }
    }

    float bias[8];
#pragma unroll
    for (int p = 0; p < 8; p++) bias[p] = b2[cg * 8 + p];

#pragma unroll
    for (int q = 0; q < 8; q++) {
        int ly = 2 * q + hi;
        float* op = g_conv2 +
                    ((size_t)(b * H2 + oh0 + ly) * W2P + (ow0 + lx)) * C2 + cg * 8;
#pragma unroll
        for (int p = 0; p < 4; p++) {
            float a0, a1;
            unpack2(acc[q][p], a0, a1);
            float2 st;
            st.x = fmaxf(a0 + bias[2 * p + 0], 0.f);
            st.y = fmaxf(a1 + bias[2 * p + 1], 0.f);
            *(float2*)(op + 2 * p) = st;
        }
    }
}

// =====================================================================
// FC1 v3 split-K: 256 CTAs, each K=1024 split into 4 groups of 256.
// Group = 64 threads: 16 jg (8 j each) x 4 bh (8 batches each).
// Thread: 8 batches x 8 j = 32 f32x2 accs. Conflict-free LDS throughout.
// =====================================================================
__global__ __launch_bounds__(256) void fc1_kernel(const float* __restrict__ w1) {
    __shared__ __align__(16) float wS[8192];        // ((g*16+kk)*2+half)*64 + jg*4 + f
    __shared__ float xS[4 * 16 * 33];               // (g*16+kk)*33 + b

    int tid   = threadIdx.x;
    int chunk = blockIdx.x;
    int kb0   = chunk * 1024;

    int g  = tid >> 6;
    int t  = tid & 63;
    int jg = t & 15;
    int bh = t >> 4;            // 0..3

    unsigned long long acc[8][4];
#pragma unroll
    for (int i = 0; i < 8; i++)
#pragma unroll
        for (int p = 0; p < 4; p++) acc[i][p] = 0ULL;

    const float4* w1v = (const float4*)w1;

    for (int rnd = 0; rnd < 16; rnd++) {
        int kbase = kb0 + rnd * 16;
        {
            float4* wSv = (float4*)wS;
            for (int i = tid; i < 2048; i += 256) {
                int jj   = i & 15;
                int half = (i >> 4) & 1;
                int kkg  = i >> 5;            // 0..63
                int kk = kkg & 15, gg = kkg >> 4;
                int k  = kbase + gg * 256 + kk;
                wSv[i] = w1v[(size_t)k * 32 + jj * 2 + half];
            }
        }
        for (int i = tid; i < 2048; i += 256) {
            int kk = i & 15;
            int bb = (i >> 4) & 31;
            int gg = i >> 9;
            xS[(gg * 16 + kk) * 33 + bb] =
                g_conv2[(size_t)bb * FLAT + kbase + gg * 256 + kk];
        }
        __syncthreads();

#pragma unroll 4
        for (int kk = 0; kk < 16; kk++) {
            const float4* wb = (const float4*)wS + (g * 16 + kk) * 32;
            ulonglong2 wA = *(const ulonglong2*)&wb[jg];
            ulonglong2 wB = *(const ulonglong2*)&wb[16 + jg];
            const float* xp = &xS[(g * 16 + kk) * 33 + bh * 8];
#pragma unroll
            for (int i = 0; i < 8; i++) {
                float x = xp[i];
                unsigned long long xx = pack2(x, x);
                acc[i][0] = ffma2(xx, wA.x, acc[i][0]);
                acc[i][1] = ffma2(xx, wA.y, acc[i][1]);
                acc[i][2] = ffma2(xx, wB.x, acc[i][2]);
                acc[i][3] = ffma2(xx, wB.y, acc[i][3]);
            }
        }
        __syncthreads();
    }

    float* pp = g_part + (size_t)(chunk * 4 + g) * (BATCH * NJ);
#pragma unroll
    for (int i = 0; i < 8; i++) {
        int bb = bh * 8 + i;
        float a0, a1, a2, a3, a4, a5, a6, a7;
        unpack2(acc[i][0], a0, a1);
        unpack2(acc[i][1], a2, a3);
        unpack2(acc[i][2], a4, a5);
        unpack2(acc[i][3], a6, a7);
        float4 s0 = {a0, a1, a2, a3};
        float4 s1 = {a4, a5, a6, a7};
        float* row = pp + bb * NJ + jg * 8;
        *(float4*)(row + 0) = s0;
        *(float4*)(row + 4) = s1;
    }
}

// reduce stage A: 1024 partials -> 16 groups (64 each)
__global__ __launch_bounds__(256) void fc1_reduceA_kernel() {
    int idx = blockIdx.x * 256 + threadIdx.x;   // 0..4095
    int gy  = blockIdx.y;                       // 0..15
    float s = 0.f;
#pragma unroll 8
    for (int c = 0; c < 64; c++)
        s += g_part[(size_t)(gy * 64 + c) * (BATCH * NJ) + idx];
    g_part2[gy * (BATCH * NJ) + idx] = s;
}

// reduce stage B: 16 -> 1, + bias + relu
__global__ __launch_bounds__(256) void fc1_reduceB_kernel(const float* __restrict__ d1) {
    int idx = blockIdx.x * 256 + threadIdx.x;   // 0..4095
    float s = 0.f;
#pragma unroll
    for (int gy = 0; gy < 16; gy++)
        s += g_part2[gy * (BATCH * NJ) + idx];
    int j = idx & 127;
    g_xfc[idx] = fmaxf(s + d1[j], 0.f);
}

// theta = x @ w2 + d2
__global__ void fc2_kernel(const float* __restrict__ w2, const float* __restrict__ d2) {
    int tid = threadIdx.x;
    if (tid >= BATCH * 6) return;
    int b = tid / 6, i = tid % 6;
    float s = d2[i];
    const float* x = g_xfc + b * NJ;
#pragma unroll 8
    for (int j = 0; j < NJ; j++) s += x[j] * w2[j * 6 + i];
    g_theta[tid] = s;
}

// =====================================================================
// grid_sample: bilinear, zero padding OOB
// =====================================================================
__global__ __launch_bounds__(256) void sample_kernel(const float* __restrict__ in,
                                                     float* __restrict__ out) {
    int pid = blockIdx.x * 256 + threadIdx.x;   // < 32*256*256
    int b   = pid >> 16;
    int rem = pid & 65535;
    int y   = rem >> 8;
    int x   = rem & 255;

    const float* th = g_theta + b * 6;
    float t0 = th[0], t1 = th[1], t2 = th[2];
    float t3 = th[3], t4 = th[4], t5 = th[5];

    float X = (2.f * (float)x + 1.f) * (1.f / 256.f) - 1.f;
    float Y = (2.f * (float)y + 1.f) * (1.f / 256.f) - 1.f;
    float gx = t0 * X + t1 * Y + t2;
    float gy = t3 * X + t4 * Y + t5;
    float px = (gx + 1.f) * 128.f - 0.5f;
    float py = (gy + 1.f) * 128.f - 0.5f;

    float x0f = floorf(px), y0f = floorf(py);
    float wx1 = px - x0f, wx0 = 1.f - wx1;
    float wy1 = py - y0f, wy0 = 1.f - wy1;
    int ix0 = (int)x0f, iy0 = (int)y0f;
    int ix1 = ix0 + 1,  iy1 = iy0 + 1;

    float o0 = 0.f, o1 = 0.f, o2 = 0.f;
    const float* base = in + (size_t)b * HIN * WIN * 3;

    {
        int yi = iy0, xi = ix0; float w = wy0 * wx0;
        if (xi >= 0 && xi < WIN && yi >= 0 && yi < HIN) {
            const float* p = base + ((size_t)yi * WIN + xi) * 3;
            o0 += w * p[0]; o1 += w * p[1]; o2 += w * p[2];
        }
    }
    {
        int yi = iy0, xi = ix1; float w = wy0 * wx1;
        if (xi >= 0 && xi < WIN && yi >= 0 && yi < HIN) {
            const float* p = base + ((size_t)yi * WIN + xi) * 3;
            o0 += w * p[0]; o1 += w * p[1]; o2 += w * p[2];
        }
    }
    {
        int yi = iy1, xi = ix0; float w = wy1 * wx0;
        if (xi >= 0 && xi < WIN && yi >= 0 && yi < HIN) {
            const float* p = base + ((size_t)yi * WIN + xi) * 3;
            o0 += w * p[0]; o1 += w * p[1]; o2 += w * p[2];
        }
    }
    {
        int yi = iy1, xi = ix1; float w = wy1 * wx1;
        if (xi >= 0 && xi < WIN && yi >= 0 && yi < HIN) {
            const float* p = base + ((size_t)yi * WIN + xi) * 3;
            o0 += w * p[0]; o1 += w * p[1]; o2 += w * p[2];
        }
    }

    float* op = out + (size_t)pid * 3;
    op[0] = o0; op[1] = o1; op[2] = o2;
}

// =====================================================================
// launch
// =====================================================================
extern "C" void kernel_launch(void* const* d_in, const int* in_sizes, int n_in,
                              void* d_out, int out_size) {
    const float* inputs = (const float*)d_in[0];
    const float* k1     = (const float*)d_in[1];
    const float* b1     = (const float*)d_in[2];
    const float* k2     = (const float*)d_in[3];
    const float* b2     = (const float*)d_in[4];
    const float* w1     = (const float*)d_in[5];
    const float* d1     = (const float*)d_in[6];
    const float* w2     = (const float*)d_in[7];
    const float* d2     = (const float*)d_in[8];
    float* out = (float*)d_out;

    static int smem_set = 0;
    if (!smem_set) {
        cudaFuncSetAttribute(conv2_kernel, cudaFuncAttributeMaxDynamicSharedMemorySize,
                             SM2_BYTES);
        smem_set = 1;
    }

    conv1_kernel<<<(BATCH * H1 * W1P) / 256, 256>>>(inputs, k1, b1);

    dim3 g2(W2P / 16, H2 / 16, BATCH);   // (4, 4, 32)
    conv2_kernel<<<g2, 256, SM2_BYTES>>>(k2, b2);

    fc1_kernel<<<NCH2, 256>>>(w1);
    dim3 gra(16, 16);
    fc1_reduceA_kernel<<<gra, 256>>>();
    fc1_reduceB_kernel<<<16, 256>>>(d1);
    fc2_kernel<<<1, 192>>>(w2, d2);

    sample_kernel<<<(BATCH * HIN * WIN) / 256, 256>>>(inputs, out);
}